// round 12
// baseline (speedup 1.0000x reference)
#include <cuda_runtime.h>
#include <cuda_fp16.h>
#include <cstdint>

#define IM_HW   16384          // 128*128 pixels
#define BC      64             // B*C channels
#define NB      10980          // 183*60 HT bins
#define NV      983040         // votes (= 3840*256 exactly)
#define CAP     256            // per-bin capacity (mean 89.5, sigma 9.4 -> 17 sigma)
#define TBLK    512            // transpose blocks in fused prep kernel
#define GGRID   592            // gather grid: 148 SMs x 4 blocks (1 wave, persistent)

__device__ __forceinline__ __half2 u2h2(unsigned u) {
    union { unsigned u; __half2 h; } c; c.u = u; return c.h;
}
__device__ __forceinline__ unsigned h22u(__half2 h) {
    union { unsigned u; __half2 h; } c; c.h = h; return c.u;
}

// -------- persistent scratch (__device__ globals; zero-initialized) --------
__device__ uint4    d_xh[IM_HW * 8];          // fp16 image [pix][64ch] = 128B/row (2 MB)
__device__ int      d_cursor[NB];             // per-bin count; re-zeroed by gather
__device__ unsigned d_packs[NB * CAP];        // packed (pix:14 | w18) per slot (11.2 MB)
__device__ int      d_ovf_cnt;
__device__ uint4    d_ovf[4096];              // overflow spill (pix<<7, wbits_f32, bin, 0)

// -------- 1. fused prep: transpose+fp16 (blocks 0..511) || fill (blocks 512+) --------
__global__ void __launch_bounds__(256) prep_kernel(const float* __restrict__ im,
                                                   const float* __restrict__ vm) {
    if (blockIdx.x < TBLK) {
        __shared__ float tile[32][68];        // pitch 272B -> float4-aligned rows
        int pixbase = blockIdx.x * 32;
        int t  = threadIdx.x;
        int tx = t & 31;
        int ty = t >> 5;
        #pragma unroll
        for (int b0 = 0; b0 < BC; b0 += 8)
            tile[tx][b0 + ty] = im[(b0 + ty) * IM_HW + pixbase + tx];   // coalesced
        __syncthreads();
        int p  = t >> 3;
        int c0 = (t & 7) * 8;
        float4 a = *(float4*)&tile[p][c0];
        float4 b = *(float4*)&tile[p][c0 + 4];
        uint4 hv;
        hv.x = h22u(__float22half2_rn(make_float2(a.x, a.y)));
        hv.y = h22u(__float22half2_rn(make_float2(a.z, a.w)));
        hv.z = h22u(__float22half2_rn(make_float2(b.x, b.y)));
        hv.w = h22u(__float22half2_rn(make_float2(b.z, b.w)));
        *(uint4*)((char*)d_xh + (pixbase + p) * 128 + c0 * 2) = hv;
    } else {
        int v = (blockIdx.x - TBLK) * 256 + threadIdx.x;   // < NV by construction
        float fp = __ldg(&vm[v * 3 + 0]);
        float fh = __ldg(&vm[v * 3 + 1]);
        float fw = __ldg(&vm[v * 3 + 2]);
        int pix = (int)fp;
        int bin = (int)fh;
        unsigned w18 = (unsigned)(fw * 262144.0f);          // w in [0,1) -> 18-bit fixed
        if (w18 > 0x3FFFFu) w18 = 0x3FFFFu;
        int pos = atomicAdd(&d_cursor[bin], 1);
        if (pos < CAP) {
            d_packs[bin * CAP + pos] = ((unsigned)pix << 18) | w18;
        } else {
            int o = atomicAdd(&d_ovf_cnt, 1);
            if (o < 4096)
                d_ovf[o] = make_uint4((unsigned)(pix << 7), __float_as_uint(fw),
                                      (unsigned)bin, 0u);
        }
    }
}

// 8-channel fp16 FMA into fp32 accumulators
__device__ __forceinline__ void fma8(float* acc, uint4 xv, float wgt) {
    float2 f0 = __half22float2(u2h2(xv.x));
    float2 f1 = __half22float2(u2h2(xv.y));
    float2 f2 = __half22float2(u2h2(xv.z));
    float2 f3 = __half22float2(u2h2(xv.w));
    acc[0] = fmaf(wgt, f0.x, acc[0]);
    acc[1] = fmaf(wgt, f0.y, acc[1]);
    acc[2] = fmaf(wgt, f1.x, acc[2]);
    acc[3] = fmaf(wgt, f1.y, acc[3]);
    acc[4] = fmaf(wgt, f2.x, acc[4]);
    acc[5] = fmaf(wgt, f2.y, acc[5]);
    acc[6] = fmaf(wgt, f3.x, acc[6]);
    acc[7] = fmaf(wgt, f3.y, acc[7]);
}

// byte address of x row from packed record: (pix<<7); mask form keeps it 1 LOP3+SHF
__device__ __forceinline__ unsigned raddr(unsigned rec) { return (rec & 0xFFFC0000u) >> 11; }
// masked weight: 0 beyond the quarter's record count (branch-free tail)
__device__ __forceinline__ float rw(unsigned rec, int j, int qcnt) {
    float w = (float)(rec & 0x3FFFFu) * 0x1p-18f;
    return j < qcnt ? w : 0.f;
}

// -------- 2. hot kernel: persistent, chunked, batch-4 gather-reduce --------
// 592 blocks (1 wave) stride over groups of 8 bins. One warp per bin; the
// bin's records are split into 4 contiguous quarter-chunks; per iteration a
// quarter fetches 4 packed records with ONE broadcast LDG.128, then issues 4
// independent 128B x-loads (warp: 16 votes in flight). Tails masked via w=0
// (stale record addresses are always valid: pix < 16384).
__global__ void __launch_bounds__(256, 4) gather_kernel(float* __restrict__ out) {
    __shared__ float sout[BC][8];
    int warp = threadIdx.x >> 5;
    int lane = threadIdx.x & 31;
    int q    = lane >> 3;                     // quarter 0..3
    const char* xb = (const char*)d_xh + (lane & 7) * 16;   // 8 fp16 channels
    int novf = d_ovf_cnt;                     // 0 in practice (benign reset below)
    if (blockIdx.x == 0 && threadIdx.x == 0) d_ovf_cnt = 0;
    if (novf > 4096) novf = 4096;

    for (int grp = blockIdx.x; grp * 8 < NB; grp += GGRID) {
        int bin0 = grp * 8;
        int bin  = bin0 + warp;
        float acc[8] = {0.f, 0.f, 0.f, 0.f, 0.f, 0.f, 0.f, 0.f};
        if (bin < NB) {
            int cnt = d_cursor[bin];
            if (lane == 0) d_cursor[bin] = 0;           // reset for next replay
            if (cnt > CAP) cnt = CAP;
            const uint4* pp4 = (const uint4*)(d_packs + (size_t)bin * CAP);
            int chunkR = ((cnt + 15) >> 4) << 2;        // records/quarter, mult of 4
            int qcnt   = cnt - q * chunkR;              // may be <=0 (masked)
            int base   = (q * chunkR) >> 2;
            int iters  = chunkR >> 2;                   // warp-uniform trip count
            for (int k = 0; k < iters; k++) {
                uint4 r4 = __ldg(&pp4[base + k]);       // 4 records, broadcast/quarter
                int j0 = 4 * k;
                unsigned a0 = raddr(r4.x), a1 = raddr(r4.y);
                unsigned a2 = raddr(r4.z), a3 = raddr(r4.w);
                uint4 x0 = *(const uint4*)(xb + a0);    // 4 independent 128B gathers
                uint4 x1 = *(const uint4*)(xb + a1);
                uint4 x2 = *(const uint4*)(xb + a2);
                uint4 x3 = *(const uint4*)(xb + a3);
                fma8(acc, x0, rw(r4.x, j0 + 0, qcnt));
                fma8(acc, x1, rw(r4.y, j0 + 1, qcnt));
                fma8(acc, x2, rw(r4.z, j0 + 2, qcnt));
                fma8(acc, x3, rw(r4.w, j0 + 3, qcnt));
            }
            for (int j = 0; j < novf; j++) {            // spill (unreachable in practice)
                uint4 ov = d_ovf[j];
                if ((int)ov.z == bin && q == 0) {
                    uint4 xv = *(const uint4*)(xb + ov.x);
                    fma8(acc, xv, __uint_as_float(ov.y));
                }
            }
        }
        // combine quarters
        #pragma unroll
        for (int k = 0; k < 8; k++) {
            acc[k] += __shfl_xor_sync(0xffffffffu, acc[k], 8);
            acc[k] += __shfl_xor_sync(0xffffffffu, acc[k], 16);
        }
        __syncthreads();                                // sout safe to rewrite
        if (lane < 8) {
            #pragma unroll
            for (int k = 0; k < 8; k++) sout[lane * 8 + k][warp] = acc[k];
        }
        __syncthreads();
        int c = threadIdx.x >> 3;
        int b = threadIdx.x & 7;
        if (bin0 + b < NB) {
            out[c * NB + bin0 + b]        = sout[c][b];
            out[(c + 32) * NB + bin0 + b] = sout[c + 32][b];
        }
    }
}

// -------- launch --------
extern "C" void kernel_launch(void* const* d_in, const int* in_sizes, int n_in,
                              void* d_out, int out_size) {
    const float* im = (const float*)d_in[0];
    const float* vm = (const float*)d_in[1];
    if (in_sizes[0] == NV * 3) { im = (const float*)d_in[1]; vm = (const float*)d_in[0]; }
    float* out = (float*)d_out;

    prep_kernel<<<TBLK + NV / 256, 256>>>(im, vm);
    gather_kernel<<<GGRID, 256>>>(out);
}